// round 6
// baseline (speedup 1.0000x reference)
#include <cuda_runtime.h>
#include <cuda_fp16.h>
#include <math.h>

#define NN 100000
#define EE 1600000
#define EPSV 1e-16f
#define NEG_SLOPE 0.2f
#define FULL 0xffffffffu
#define G1B 1563          // gemm1 blocks in fusedA
#define HB  1024          // hist blocks in fusedA

// ---------------- scratch (device globals; allocation-free) ----------------
__device__ __half2 g_h1h[NN * 64];     // h1 [N,128] fp16       25.6 MB
__device__ float   g_as1[NN * 8];      // alpha_src1 [N,8]       3.2 MB
__device__ float   g_ad1[NN * 8];      // alpha_dst1 [N,8]       3.2 MB
__device__ float4  g_out1[NN * 32];    // elu(out1) [N,128]     51.2 MB
__device__ float4  g_g2[NN * 10];      // g2 [N,40]               16 MB
__device__ float   g_as2[NN];          // alpha_src2 [N]
__device__ float   g_ad2[NN];          // alpha_dst2 [N]
// CSR sort scratch (self-cleaning across runs)
__device__ int     g_deg[NN];          // zero-init .bss; drained by scatter
__device__ int     g_off[NN + 1];
__device__ int     g_ssrc[EE];         // src sorted by dst      6.4 MB
__device__ int          g_psum[98];
__device__ volatile int g_flag[98];    // zero-init; reader resets

// ---------------- helpers ----------------
__device__ __forceinline__ void fma4(float4& a, float s, float4 b) {
    a.x += s * b.x; a.y += s * b.y; a.z += s * b.z; a.w += s * b.w;
}
__device__ __forceinline__ float dot4(float4 a, float4 b) {
    return a.x * b.x + a.y * b.y + a.z * b.z + a.w * b.w;
}
__device__ __forceinline__ float leaky_exp(float e) {
    float t = e > 0.f ? e : NEG_SLOPE * e;
    return __expf(t);
}

// ---------------- 1. fusedA: gemm1 (blocks 0..G1B) | dst-hist (rest) --------
// gemm1: 64 nodes x 128 cols register-tiled, whole W1 + x tile in 96KB smem.
// epilogue stores h1 as fp16 and the per-head alpha dot products.
__global__ __launch_bounds__(256) void fusedA_kernel(
    const float* __restrict__ x, const float* __restrict__ W1,
    const float* __restrict__ a_src, const float* __restrict__ a_dst,
    const int* __restrict__ dst)
{
    if (blockIdx.x >= G1B) {              // ---- histogram part ----
        int i = (blockIdx.x - G1B) * 256 + threadIdx.x;
        #pragma unroll 2
        for (; i < EE; i += HB * 256)
            atomicAdd(&g_deg[__ldcs(dst + i)], 1);
        return;
    }
    // ---- gemm1 part ----
    extern __shared__ float smem[];
    float4* sW4 = (float4*)smem;                 // [k*32 + c4]  64 KB
    float4* sx4 = (float4*)(smem + 128 * 128);   // [n*32 + k4]  32 KB
    const int tid = threadIdx.x;
    const int cx = tid & 31;      // col quad
    const int ny = tid >> 5;      // node group of 8
    const int nbase = blockIdx.x * 64;
    const float4* W4 = (const float4*)W1;
    const float4* x4 = (const float4*)x;

    #pragma unroll
    for (int it = 0; it < 16; it++)              // W: 4096 f4
        sW4[tid + it * 256] = W4[tid + it * 256];
    #pragma unroll
    for (int it = 0; it < 8; it++) {             // x: 2048 f4
        int f = tid + it * 256;
        int gn = nbase + (f >> 5);
        sx4[f] = (gn < NN) ? x4[(size_t)gn * 32 + (f & 31)]
                           : make_float4(0.f, 0.f, 0.f, 0.f);
    }
    __syncthreads();

    float4 c[8];
    #pragma unroll
    for (int i = 0; i < 8; i++) c[i] = make_float4(0.f, 0.f, 0.f, 0.f);

    #pragma unroll 4
    for (int k = 0; k < 128; k += 4) {
        float4 w0 = sW4[(k + 0) * 32 + cx];
        float4 w1 = sW4[(k + 1) * 32 + cx];
        float4 w2 = sW4[(k + 2) * 32 + cx];
        float4 w3 = sW4[(k + 3) * 32 + cx];
        #pragma unroll
        for (int i = 0; i < 8; i++) {
            float4 xv = sx4[(ny * 8 + i) * 32 + (k >> 2)];   // warp broadcast
            fma4(c[i], xv.x, w0); fma4(c[i], xv.y, w1);
            fma4(c[i], xv.z, w2); fma4(c[i], xv.w, w3);
        }
    }

    const int head = cx >> 2, cq = cx & 3;
    const float4 asv = ((const float4*)a_src)[head * 4 + cq];
    const float4 adv = ((const float4*)a_dst)[head * 4 + cq];
    #pragma unroll
    for (int i = 0; i < 8; i++) {
        int gn = nbase + ny * 8 + i;
        float ps = dot4(c[i], asv);
        float pd = dot4(c[i], adv);
        ps += __shfl_xor_sync(FULL, ps, 1); ps += __shfl_xor_sync(FULL, ps, 2);
        pd += __shfl_xor_sync(FULL, pd, 1); pd += __shfl_xor_sync(FULL, pd, 2);
        if (gn < NN) {
            __half2 p0 = __floats2half2_rn(c[i].x, c[i].y);
            __half2 p1 = __floats2half2_rn(c[i].z, c[i].w);
            uint2 pk = make_uint2(*(unsigned*)&p0, *(unsigned*)&p1);
            *(uint2*)&g_h1h[gn * 64 + 2 * cx] = pk;
            if (cq == 0) { g_as1[gn * 8 + head] = ps; g_ad1[gn * 8 + head] = pd; }
        }
    }
}

// ---------------- 2. domino scan: g_off = exclusive_scan(g_deg) -------------
// 98 blocks x 1024 threads, all resident (98 < 148 SMs) -> spin-safe.
__global__ __launch_bounds__(1024) void scan_kernel() {
    const int t = threadIdx.x;
    const int b = blockIdx.x;
    const int i = b * 1024 + t;
    int v = (i < NN) ? g_deg[i] : 0;
    int lane = t & 31, w = t >> 5;
    int xv = v;
    #pragma unroll
    for (int o = 1; o < 32; o <<= 1) {
        int y = __shfl_up_sync(FULL, xv, o);
        if (lane >= o) xv += y;
    }
    __shared__ int wt[32];
    __shared__ int blockpre;
    if (lane == 31) wt[w] = xv;
    __syncthreads();
    if (w == 0) {
        int z = wt[lane];
        #pragma unroll
        for (int o = 1; o < 32; o <<= 1) {
            int y = __shfl_up_sync(FULL, z, o);
            if (lane >= o) z += y;
        }
        wt[lane] = z;
    }
    __syncthreads();
    const int total = wt[31];
    if (t == 0) {                       // domino chain
        int pre = 0;
        if (b > 0) {
            while (g_flag[b - 1] == 0) { }
            __threadfence();
            pre = g_psum[b - 1];
            g_flag[b - 1] = 0;          // self-clean for next run
        }
        blockpre = pre;
        if (b < 97) {
            g_psum[b] = pre + total;
            __threadfence();
            g_flag[b] = 1;
        }
    }
    __syncthreads();
    int pre = blockpre + (w ? wt[w - 1] : 0);
    if (i < NN) g_off[i] = pre + xv - v;
    if (i == NN - 1) g_off[NN] = EE;
}

// ---------------- 3. scatter src into CSR order (drains g_deg to 0) ---------
__global__ __launch_bounds__(256) void scatter_kernel(
    const int* __restrict__ src, const int* __restrict__ dst)
{
    int i = blockIdx.x * 256 + threadIdx.x;
    int d = __ldcs(dst + i);
    int s = __ldcs(src + i);
    int p = g_off[d] + atomicSub(&g_deg[d], 1) - 1;
    __stcs(&g_ssrc[p], s);
}

// ---------------- 4. L1 fused aggregate: warp per node, one pass, fp16 h ----
__global__ __launch_bounds__(256) void agg1_kernel(const float* __restrict__ b1)
{
    const int n = (blockIdx.x * 256 + threadIdx.x) >> 5;   // node (grid exact)
    const int l = threadIdx.x & 31;
    const int beg = g_off[n], end = g_off[n + 1];
    const int head = l >> 2;
    const float adp = g_ad1[n * 8 + head];
    const uint2* h16 = (const uint2*)g_h1h;      // [n*32 + l] -> 4 halves

    float den = 0.f;
    float4 acc = make_float4(0.f, 0.f, 0.f, 0.f);

    for (int base = beg; base < end; base += 32) {
        const int je = min(32, end - base);
        const int sj = (l < je) ? __ldg(&g_ssrc[base + l]) : 0;
        int k = 0;
        #pragma unroll 1
        for (; k + 4 <= je; k += 4) {
            int s0 = __shfl_sync(FULL, sj, k);
            int s1 = __shfl_sync(FULL, sj, k + 1);
            int s2 = __shfl_sync(FULL, sj, k + 2);
            int s3 = __shfl_sync(FULL, sj, k + 3);
            float e0 = leaky_exp(__ldg(&g_as1[s0 * 8 + head]) + adp);
            float e1 = leaky_exp(__ldg(&g_as1[s1 * 8 + head]) + adp);
            float e2 = leaky_exp(__ldg(&g_as1[s2 * 8 + head]) + adp);
            float e3 = leaky_exp(__ldg(&g_as1[s3 * 8 + head]) + adp);
            uint2 p0 = __ldg(&h16[s0 * 32 + l]);
            uint2 p1 = __ldg(&h16[s1 * 32 + l]);
            uint2 p2 = __ldg(&h16[s2 * 32 + l]);
            uint2 p3 = __ldg(&h16[s3 * 32 + l]);
            den += (e0 + e1) + (e2 + e3);
            float2 a0 = __half22float2(*(__half2*)&p0.x), b0 = __half22float2(*(__half2*)&p0.y);
            float2 a1 = __half22float2(*(__half2*)&p1.x), b1v = __half22float2(*(__half2*)&p1.y);
            float2 a2 = __half22float2(*(__half2*)&p2.x), b2v = __half22float2(*(__half2*)&p2.y);
            float2 a3 = __half22float2(*(__half2*)&p3.x), b3 = __half22float2(*(__half2*)&p3.y);
            acc.x += e0 * a0.x + e1 * a1.x + e2 * a2.x + e3 * a3.x;
            acc.y += e0 * a0.y + e1 * a1.y + e2 * a2.y + e3 * a3.y;
            acc.z += e0 * b0.x + e1 * b1v.x + e2 * b2v.x + e3 * b3.x;
            acc.w += e0 * b0.y + e1 * b1v.y + e2 * b2v.y + e3 * b3.y;
        }
        for (; k < je; k++) {
            int s = __shfl_sync(FULL, sj, k);
            float e = leaky_exp(__ldg(&g_as1[s * 8 + head]) + adp);
            den += e;
            uint2 p = __ldg(&h16[s * 32 + l]);
            float2 a = __half22float2(*(__half2*)&p.x);
            float2 b = __half22float2(*(__half2*)&p.y);
            acc.x += e * a.x; acc.y += e * a.y;
            acc.z += e * b.x; acc.w += e * b.y;
        }
    }
    const float rinv = 1.f / (den + EPSV);
    float4 v = ((const float4*)b1)[l];
    v.x += acc.x * rinv; v.y += acc.y * rinv;
    v.z += acc.z * rinv; v.w += acc.w * rinv;
    v.x = v.x > 0.f ? v.x : __expf(v.x) - 1.f;
    v.y = v.y > 0.f ? v.y : __expf(v.y) - 1.f;
    v.z = v.z > 0.f ? v.z : __expf(v.z) - 1.f;
    v.w = v.w > 0.f ? v.w : __expf(v.w) - 1.f;
    g_out1[n * 32 + l] = v;
}

// ---------------- 5. GEMM2: g2 = elu_h @ W2 [128->40] + scalar alphas -------
__global__ __launch_bounds__(256) void gemm2_kernel(
    const float* __restrict__ W2, const float* __restrict__ a_src,
    const float* __restrict__ a_dst)
{
    __shared__ float4 sW[128 * 10];
    __shared__ float4 sas[10], sad[10];
    __shared__ float  sx[256 * 17];
    const int tid = threadIdx.x;
    const int node = blockIdx.x * 256 + tid;
    const float4* W4 = (const float4*)W2;
    #pragma unroll
    for (int it = 0; it < 5; it++) sW[tid + it * 256] = W4[tid + it * 256];
    if (tid < 10) { sas[tid] = ((const float4*)a_src)[tid];
                    sad[tid] = ((const float4*)a_dst)[tid]; }
    const float* hin = (const float*)g_out1;

    float4 acc[10];
    #pragma unroll
    for (int j = 0; j < 10; j++) acc[j] = make_float4(0, 0, 0, 0);

    for (int kc = 0; kc < 8; kc++) {
        __syncthreads();
        #pragma unroll
        for (int it = 0; it < 16; it++) {
            int f = tid + it * 256;
            int nl2 = f >> 4, k = f & 15;
            int gn = blockIdx.x * 256 + nl2;
            sx[nl2 * 17 + k] = (gn < NN) ? hin[(size_t)gn * 128 + kc * 16 + k] : 0.f;
        }
        __syncthreads();
        #pragma unroll
        for (int k = 0; k < 16; k++) {
            float xv = sx[tid * 17 + k];
            const float4* wr = &sW[(kc * 16 + k) * 10];
            #pragma unroll
            for (int j = 0; j < 10; j++) fma4(acc[j], xv, wr[j]);
        }
    }
    if (node < NN) {
        float s = 0.f, d = 0.f;
        #pragma unroll
        for (int j = 0; j < 10; j++) { s += dot4(acc[j], sas[j]); d += dot4(acc[j], sad[j]); }
        #pragma unroll
        for (int j = 0; j < 10; j++) g_g2[node * 10 + j] = acc[j];
        g_as2[node] = s;
        g_ad2[node] = d;
    }
}

// ---------------- 6. L2 fused aggregate (one pass) + bias + log_softmax -----
__global__ __launch_bounds__(256) void agg2_kernel(
    const float* __restrict__ b2, float* __restrict__ out)
{
    const int n = (blockIdx.x * 256 + threadIdx.x) >> 5;
    const int l = threadIdx.x & 31;
    const int beg = g_off[n], end = g_off[n + 1];
    const float ad2n = g_ad2[n];
    const bool act = l < 10;

    float den = 0.f;
    float4 acc = make_float4(0.f, 0.f, 0.f, 0.f);

    for (int base = beg; base < end; base += 32) {
        const int je = min(32, end - base);
        const int sj = (l < je) ? __ldg(&g_ssrc[base + l]) : 0;
        int k = 0;
        #pragma unroll 1
        for (; k + 4 <= je; k += 4) {
            int s0 = __shfl_sync(FULL, sj, k);
            int s1 = __shfl_sync(FULL, sj, k + 1);
            int s2 = __shfl_sync(FULL, sj, k + 2);
            int s3 = __shfl_sync(FULL, sj, k + 3);
            float e0 = leaky_exp(__ldg(&g_as2[s0]) + ad2n);
            float e1 = leaky_exp(__ldg(&g_as2[s1]) + ad2n);
            float e2 = leaky_exp(__ldg(&g_as2[s2]) + ad2n);
            float e3 = leaky_exp(__ldg(&g_as2[s3]) + ad2n);
            den += (e0 + e1) + (e2 + e3);
            if (act) {
                fma4(acc, e0, g_g2[s0 * 10 + l]);
                fma4(acc, e1, g_g2[s1 * 10 + l]);
                fma4(acc, e2, g_g2[s2 * 10 + l]);
                fma4(acc, e3, g_g2[s3 * 10 + l]);
            }
        }
        for (; k < je; k++) {
            int s = __shfl_sync(FULL, sj, k);
            float e = leaky_exp(__ldg(&g_as2[s]) + ad2n);
            den += e;
            if (act) fma4(acc, e, g_g2[s * 10 + l]);
        }
    }
    const float rinv = 1.f / (den + EPSV);

    float4 v = make_float4(-1e30f, -1e30f, -1e30f, -1e30f);
    if (act) {
        v = ((const float4*)b2)[l];
        v.x += acc.x * rinv; v.y += acc.y * rinv;
        v.z += acc.z * rinv; v.w += acc.w * rinv;
    }
    float mx = act ? fmaxf(fmaxf(v.x, v.y), fmaxf(v.z, v.w)) : -1e30f;
    #pragma unroll
    for (int o = 16; o; o >>= 1) mx = fmaxf(mx, __shfl_xor_sync(FULL, mx, o));
    float sm = 0.f;
    if (act) sm = __expf(v.x - mx) + __expf(v.y - mx) + __expf(v.z - mx) + __expf(v.w - mx);
    #pragma unroll
    for (int o = 16; o; o >>= 1) sm += __shfl_xor_sync(FULL, sm, o);
    float lse = mx + logf(sm);
    if (act)
        ((float4*)out)[n * 10 + l] =
            make_float4(v.x - lse, v.y - lse, v.z - lse, v.w - lse);
}

// ---------------- launch ----------------
extern "C" void kernel_launch(void* const* d_in, const int* in_sizes, int n_in,
                              void* d_out, int out_size)
{
    const float* x      = (const float*)d_in[0];
    const int*   eidx   = (const int*)d_in[1];
    const float* W1     = (const float*)d_in[2];
    const float* a_src1 = (const float*)d_in[3];
    const float* a_dst1 = (const float*)d_in[4];
    const float* b1     = (const float*)d_in[5];
    const float* W2     = (const float*)d_in[6];
    const float* a_src2 = (const float*)d_in[7];
    const float* a_dst2 = (const float*)d_in[8];
    const float* b2     = (const float*)d_in[9];
    const int* src = eidx;
    const int* dst = eidx + EE;
    float* out = (float*)d_out;

    const int G1_SMEM = (128 * 128 + 64 * 128) * 4;   // 96 KB
    (void)cudaFuncSetAttribute(fusedA_kernel,
                               cudaFuncAttributeMaxDynamicSharedMemorySize, G1_SMEM);

    fusedA_kernel<<<G1B + HB, 256, G1_SMEM>>>(x, W1, a_src1, a_dst1, dst); // 1
    scan_kernel<<<98, 1024>>>();                                           // 2
    scatter_kernel<<<EE / 256, 256>>>(src, dst);                           // 3
    agg1_kernel<<<NN / 8, 256>>>(b1);                                      // 4 (ncu)
    gemm2_kernel<<<(NN + 255) / 256, 256>>>(W2, a_src2, a_dst2);           // 5
    agg2_kernel<<<NN / 8, 256>>>(b2, out);                                 // 6
}